// round 14
// baseline (speedup 1.0000x reference)
#include <cuda_runtime.h>
#include <cstdint>

#define BATCH 4
#define CIN   64
#define COUT  64
#define HW    224
#define NPIX  (HW * HW)          // 50176
#define KK    9
#define NBINS 10
#define KTOT  (CIN * KK)         // 576
#define KC    96
#define NCHUNK (KTOT / KC)       // 6
#define KSTEPS 6                 // k16-steps per chunk
#define TILE_M 128
#define NTILE (NPIX / TILE_M)    // 392
#define NCONV (BATCH * NTILE)    // 1568
#define Y_ELEMS (BATCH * COUT * NPIX)
#define ESTRIDE 132              // epilogue smem stride (conflict-free)

// dynamic smem: sA 2x1536 uint4 (49152 B) + tab (2304 B); E (33792 B) aliases
#define SA_BUFSTRIDE 1536
#define TAB_OFF 49152
#define SMEM_SZ (49152 + 2304)

// B fragments as uint4: [spair 18][nt 8][lane 32] -> (ks0.r0, ks0.r1, ks1.r0, ks1.r1)
__device__ uint4 g_wfrag[18 * 8 * 32];

__device__ __forceinline__ uint32_t pack_f16x2(float lo, float hi) {
    uint32_t d;
    asm("cvt.rn.f16x2.f32 %0, %1, %2;" : "=r"(d) : "f"(hi), "f"(lo));
    return d;
}

#define MMA_F16(d, a, b0, b1) \
    asm volatile("mma.sync.aligned.m16n8k16.row.col.f32.f16.f16.f32 " \
        "{%0,%1,%2,%3}, {%4,%5,%6,%7}, {%8,%9}, {%0,%1,%2,%3};" \
        : "+f"((d)[0]), "+f"((d)[1]), "+f"((d)[2]), "+f"((d)[3]) \
        : "r"((a).x), "r"((a).y), "r"((a).z), "r"((a).w), \
          "r"(b0), "r"(b1))

// ---------------------------------------------------------------------------
// Repack W (64,576) -> paired m16n8k16 B-fragment order fp16; zero hist out.
// ---------------------------------------------------------------------------
__global__ void repack_w_kernel(const float* __restrict__ w,
                                float* __restrict__ out_hist) {
    int idx = blockIdx.x * blockDim.x + threadIdx.x;
    if (idx < 18 * 8 * 32 * 4) {
        int reg  = idx & 1;
        int ks   = (idx >> 1) & 1;
        int lane = (idx >> 2) & 31;
        int nt   = (idx >> 7) & 7;
        int sp   = idx >> 10;
        int n = nt * 8 + (lane >> 2);
        int k = sp * 32 + ks * 16 + (lane & 3) * 2 + reg * 8;
        float w0 = __ldg(&w[n * KTOT + k]);
        float w1 = __ldg(&w[n * KTOT + k + 1]);
        ((uint32_t*)g_wfrag)[((sp * 8 + nt) * 32 + lane) * 4 + ks * 2 + reg] =
            pack_f16x2(w0, w1);
    }
    if (idx < CIN * NBINS) out_hist[idx] = 0.0f;
}

// ---------------------------------------------------------------------------
// Implicit-GEMM conv via mma.sync fp16 (m16n8k16), f32 accumulate.
// CTA: 128 px x 64 couts, 256 threads, 8 warps: (w&3)->M 32, (w>>2)->N 32.
// KC=96: 6 chunks, ONE barrier each. Producer warp w stages m-tile w's
// fragments for all 6 k16-steps (6 x uint4 per thread). B as uint4 pairs.
// ---------------------------------------------------------------------------
__global__ __launch_bounds__(256, 2)
void conv_mma_kernel(const float* __restrict__ x,
                     const float* __restrict__ bias,
                     float* __restrict__ y) {
    extern __shared__ __align__(16) char dsm[];
    uint4* sA  = (uint4*)dsm;                 // [buf][(mt*6+ks)*32+lane]
    int*   tab = (int*)(dsm + TAB_OFF);
    float* E   = (float*)dsm;                 // epilogue alias

    const int tid  = threadIdx.x;
    const int w    = tid >> 5;
    const int lane = tid & 31;
    const int g    = lane >> 2;
    const int klo  = lane & 3;

    for (int i = tid; i < KTOT; i += 256) {
        int ci = i / 9, tap = i - ci * 9;
        int dh = tap / 3, dw = tap - dh * 3;
        tab[i] = (ci * NPIX + dh * HW + dw) | (tap << 24);
    }

    const int b    = blockIdx.x / NTILE;
    const int pix0 = (blockIdx.x % NTILE) * TILE_M;
    const float* xb = x + (size_t)b * CIN * NPIX;

    // ---- producer pixel slots: rows g and g+8 of m-tile w ----
    const float* ptrP[2];
    unsigned tmaskP[2];
    #pragma unroll
    for (int half = 0; half < 2; half++) {
        int m  = w * 16 + g + half * 8;
        int pm = pix0 + m;
        int hm = pm / HW, wm = pm - hm * HW;
        ptrP[half] = xb + hm * HW + wm - (HW + 1);
        int mk = 2 | 16;
        if (hm > 0)      mk |= 1;
        if (hm + 1 < HW) mk |= 4;
        if (wm > 0)      mk |= 8;
        if (wm + 1 < HW) mk |= 32;
        unsigned tm = 0;
        #pragma unroll
        for (int t = 0; t < 9; t++) {
            int dh = t / 3, dw = t - dh * 3;
            if (((mk >> dh) & 1) && ((mk >> (3 + dw)) & 1)) tm |= 1u << t;
        }
        tmaskP[half] = tm;
    }

    __syncthreads();   // tab ready

    const int kb = 2 * klo;

    // stage 6 fragments (one per k16-step) for chunk c
    auto loadA = [&](int c, uint4* S) {
        #pragma unroll
        for (int ks = 0; ks < KSTEPS; ks++) {
            float v[2][4];
            #pragma unroll
            for (int j = 0; j < 4; j++) {
                const int koff = ks * 16 + kb + (j & 1) + (j >> 1) * 8;
                const int e    = tab[c * KC + koff];
                const int off  = e & 0xFFFFFF;
                const int tap  = e >> 24;
                #pragma unroll
                for (int h = 0; h < 2; h++)
                    v[h][j] = ((tmaskP[h] >> tap) & 1u) ? __ldg(ptrP[h] + off)
                                                        : 0.0f;
            }
            S[ks] = make_uint4(
                pack_f16x2(v[0][0], v[0][1]), pack_f16x2(v[1][0], v[1][1]),
                pack_f16x2(v[0][2], v[0][3]), pack_f16x2(v[1][2], v[1][3]));
        }
    };

    const int wm2 = (w & 3) * 2;
    const int wn4 = (w >> 2) * 4;

    float d[2][4][4];
    #pragma unroll
    for (int mt = 0; mt < 2; mt++)
        #pragma unroll
        for (int nt = 0; nt < 4; nt++)
            #pragma unroll
            for (int k = 0; k < 4; k++) d[mt][nt][k] = 0.0f;

    uint4 S[KSTEPS];
    loadA(0, S);

    for (int c = 0; c < NCHUNK; c++) {
        const int p = c & 1;
        #pragma unroll
        for (int ks = 0; ks < KSTEPS; ks++)
            sA[p * SA_BUFSTRIDE + (w * KSTEPS + ks) * 32 + lane] = S[ks];
        __syncthreads();
        if (c + 1 < NCHUNK) loadA(c + 1, S);

        #pragma unroll
        for (int kp = 0; kp < 3; kp++) {           // k16-step pairs
            const int sp = c * 3 + kp;
            uint4 Bq[4];
            #pragma unroll
            for (int nt = 0; nt < 4; nt++)
                Bq[nt] = __ldg(&g_wfrag[(sp * 8 + wn4 + nt) * 32 + lane]);
            #pragma unroll
            for (int ks = 0; ks < 2; ks++) {
                uint4 A0 = sA[p * SA_BUFSTRIDE +
                              (wm2 * KSTEPS + kp * 2 + ks) * 32 + lane];
                uint4 A1 = sA[p * SA_BUFSTRIDE +
                              ((wm2 + 1) * KSTEPS + kp * 2 + ks) * 32 + lane];
                #pragma unroll
                for (int nt = 0; nt < 4; nt++) {
                    uint32_t b0 = ks ? Bq[nt].z : Bq[nt].x;
                    uint32_t b1 = ks ? Bq[nt].w : Bq[nt].y;
                    MMA_F16(d[0][nt], A0, b0, b1);
                    MMA_F16(d[1][nt], A1, b0, b1);
                }
            }
        }
    }

    // ---- epilogue: stage via smem for coalesced 128B stores ----
    float breg[8];
    #pragma unroll
    for (int i = 0; i < 8; i++) breg[i] = __ldg(&bias[w * 8 + i]);
    __syncthreads();                         // all smem reads done; reuse as E

    const int rbase = (w & 3) * 32 + g;
    const int cbase = wn4 * 8 + klo * 2;
    #pragma unroll
    for (int mt = 0; mt < 2; mt++) {
        #pragma unroll
        for (int nt = 0; nt < 4; nt++) {
            int r0 = rbase + mt * 16;
            int c0 = cbase + nt * 8;
            E[c0 * ESTRIDE + r0]           = d[mt][nt][0];
            E[(c0 + 1) * ESTRIDE + r0]     = d[mt][nt][1];
            E[c0 * ESTRIDE + r0 + 8]       = d[mt][nt][2];
            E[(c0 + 1) * ESTRIDE + r0 + 8] = d[mt][nt][3];
        }
    }
    __syncthreads();

    float* yb = y + (size_t)b * COUT * NPIX + pix0;
    const int p4 = lane * 4;
    #pragma unroll
    for (int i = 0; i < 8; i++) {
        int co = w * 8 + i;
        float4 v = *(const float4*)&E[co * ESTRIDE + p4];
        float bv = breg[i];
        v.x += bv; v.y += bv; v.z += bv; v.w += bv;
        *(float4*)&yb[(size_t)co * NPIX + p4] = v;
    }
}

// ---------------------------------------------------------------------------
// Histogram: warp-ballot byte-SIMD separable window-sum, direct float output.
// ---------------------------------------------------------------------------
__device__ __forceinline__ unsigned zprow_calc(unsigned nib, int l) {
    unsigned nl = __shfl_sync(0xFFFFFFFFu, nib, (l == 0) ? 29 : (l - 1));
    unsigned nr = __shfl_sync(0xFFFFFFFFu, nib, (l == 27) ? 28 : ((l + 1) & 31));
    unsigned ext = ((nl >> 3) & 1u) | (nib << 1) | ((nr & 1u) << 5);
    unsigned z0 = __popc(ext & 7u);
    unsigned z1 = __popc((ext >> 1) & 7u);
    unsigned z2 = __popc((ext >> 2) & 7u);
    unsigned z3 = __popc((ext >> 3) & 7u);
    return z0 | (z1 << 8) | (z2 << 16) | (z3 << 24);
}

__global__ __launch_bounds__(256)
void hist_count_kernel(const float* __restrict__ x, const float* __restrict__ w,
                       float* __restrict__ out_hist) {
    const int bid = blockIdx.x;
    const int rc = bid & 3;
    const int c  = (bid >> 2) & 63;
    const int b  = bid >> 8;

    __shared__ int sbin[NBINS];
    const int tid = threadIdx.x;
    if (tid < NBINS) sbin[tid] = 0;

    bool anywz = false;
    #pragma unroll
    for (int k = 0; k < KK; k++) anywz |= (__ldg(&w[c * KK + k]) == 0.0f);
    __syncthreads();

    const float* xp = x + (size_t)(b * CIN + c) * NPIX;

    if (!anywz) {
        const int wd = tid >> 5, l = tid & 31;
        const int half = wd & 1, sub = wd >> 1;
        const int r0 = rc * 56 + sub * 14;
        int colb; bool ldok;
        if (l < 28)      { colb = 112 * half + 4 * l;  ldok = true; }
        else if (l == 28){ colb = 112 * half + 112;    ldok = (half == 0); }
        else if (l == 29){ colb = 112 * half - 4;      ldok = (half == 1); }
        else             { colb = 0;                   ldok = false; }

        auto vget = [&](int row) -> float4 {
            if (ldok && row >= 0 && row < HW)
                return __ldg((const float4*)(xp + row * HW + colb));
            return make_float4(1.f, 1.f, 1.f, 1.f);
        };
        auto nibof = [&](int row, float4 v) -> unsigned {
            if (!ldok || row < 0 || row >= HW) return 0xFu;
            return (v.x == 0.f ? 1u : 0u) | (v.y == 0.f ? 2u : 0u) |
                   (v.z == 0.f ? 4u : 0u) | (v.w == 0.f ? 8u : 0u);
        };

        int cnt0 = 0;
        float4 va = vget(r0 - 1);
        float4 vb = vget(r0);
        float4 vnext = vget(r0 + 1);
        unsigned zpm = zprow_calc(nibof(r0 - 1, va), l);
        unsigned zpc = zprow_calc(nibof(r0, vb), l);

        for (int r = r0; r < r0 + 14; r++) {
            float4 vd = vget(r + 2);
            unsigned zpn = zprow_calc(nibof(r + 1, vnext), l);
            unsigned z4 = zpm + zpc + zpn;   // byte-SIMD (max 9/byte)
            if (l < 28) {
                if (z4 == 0) cnt0 += 4;
                else {
                    #pragma unroll
                    for (int j = 0; j < 4; j++) {
                        unsigned bz = (z4 >> (8 * j)) & 0xFFu;
                        if (bz == 0) cnt0++;
                        else atomicAdd(&sbin[bz], 1);
                    }
                }
            }
            zpm = zpc; zpc = zpn; vnext = vd;
        }
        if (l < 28 && cnt0) atomicAdd(&sbin[0], cnt0);
    } else {
        bool wz[KK];
        #pragma unroll
        for (int k = 0; k < KK; k++) wz[k] = (__ldg(&w[c * KK + k]) == 0.0f);
        const int col = tid;
        const int r0q = rc * 56;
        if (col < HW) {
            for (int row = r0q; row < r0q + 56; row++) {
                int z = 0;
                #pragma unroll
                for (int kh = 0; kh < 3; kh++)
                    #pragma unroll
                    for (int kw = 0; kw < 3; kw++) {
                        int gy = row + kh - 1, gx = col + kw - 1;
                        bool zero = (gy < 0 || gy >= HW || gx < 0 || gx >= HW)
                            ? true
                            : (wz[kh * 3 + kw] || __ldg(&xp[gy * HW + gx]) == 0.0f);
                        z += zero ? 1 : 0;
                    }
                atomicAdd(&sbin[z], 1);
            }
        }
    }

    __syncthreads();
    if (tid < NBINS && sbin[tid])
        atomicAdd(&out_hist[c * NBINS + tid], (float)sbin[tid]);
}

// no-op padding kernel: shifts launch order so ncu's capture (launch #8)
// lands on conv_mma_kernel
__global__ void nop_kernel() {}

// ---------------------------------------------------------------------------
extern "C" void kernel_launch(void* const* d_in, const int* in_sizes, int n_in,
                              void* d_out, int out_size) {
    const float* x    = (const float*)d_in[0];   // (4,64,224,224)
    const float* wgt  = (const float*)d_in[1];   // (64,64,3,3)
    const float* bias = (const float*)d_in[2];   // (64,)
    float* y    = (float*)d_out;
    float* hist = (float*)d_out + (size_t)Y_ELEMS;

    static int smem_set = 0;
    if (!smem_set) {
        cudaFuncSetAttribute(conv_mma_kernel,
                             cudaFuncAttributeMaxDynamicSharedMemorySize,
                             SMEM_SZ);
        smem_set = 1;
    }

    // order chosen so launch #8 (ncu capture point) is conv_mma_kernel
    repack_w_kernel<<<(18 * 8 * 32 * 4 + 255) / 256, 256>>>(wgt, hist);
    nop_kernel<<<1, 32>>>();
    hist_count_kernel<<<BATCH * CIN * 4, 256>>>(x, wgt, hist);
    conv_mma_kernel<<<NCONV, 256, SMEM_SZ>>>(x, bias, y);
}

// round 15
// speedup vs baseline: 1.0461x; 1.0461x over previous
#include <cuda_runtime.h>
#include <cstdint>

#define BATCH 4
#define CIN   64
#define COUT  64
#define HW    224
#define NPIX  (HW * HW)          // 50176
#define KK    9
#define NBINS 10
#define KTOT  (CIN * KK)         // 576
#define KC    96
#define NCHUNK (KTOT / KC)       // 6
#define TILE_M 128
#define NTILE (NPIX / TILE_M)    // 392
#define NCONV (BATCH * NTILE)    // 1568
#define Y_ELEMS (BATCH * COUT * NPIX)
#define ESTRIDE 132              // epilogue smem stride (conflict-free)

#define MPITCH 132               // A-buffer pixel pitch (conflict-free: 132%32=4)
#define BUFW   (KC * MPITCH)     // floats per buffer (12672)
#define SMEM_SZ (2 * BUFW * 4)   // 101376 B

// B fragments as uint4: [sp 18][nt 8][lane 32] -> (ks0.r0, ks0.r1, ks1.r0, ks1.r1)
__device__ uint4 g_wfrag[18 * 8 * 32];

__device__ __forceinline__ uint32_t pack_f16x2(float lo, float hi) {
    uint32_t d;
    asm("cvt.rn.f16x2.f32 %0, %1, %2;" : "=r"(d) : "f"(hi), "f"(lo));
    return d;
}

#define MMA_F16(d, a, b0, b1) \
    asm volatile("mma.sync.aligned.m16n8k16.row.col.f32.f16.f16.f32 " \
        "{%0,%1,%2,%3}, {%4,%5,%6,%7}, {%8,%9}, {%0,%1,%2,%3};" \
        : "+f"((d)[0]), "+f"((d)[1]), "+f"((d)[2]), "+f"((d)[3]) \
        : "r"((a).x), "r"((a).y), "r"((a).z), "r"((a).w), \
          "r"(b0), "r"(b1))

// ---------------------------------------------------------------------------
// Repack W (64,576) -> paired m16n8k16 B-fragment order fp16; zero hist out.
// ---------------------------------------------------------------------------
__global__ void repack_w_kernel(const float* __restrict__ w,
                                float* __restrict__ out_hist) {
    int idx = blockIdx.x * blockDim.x + threadIdx.x;
    if (idx < 18 * 8 * 32 * 4) {
        int reg  = idx & 1;
        int ks   = (idx >> 1) & 1;
        int lane = (idx >> 2) & 31;
        int nt   = (idx >> 7) & 7;
        int sp   = idx >> 10;
        int n = nt * 8 + (lane >> 2);
        int k = sp * 32 + ks * 16 + (lane & 3) * 2 + reg * 8;
        float w0 = __ldg(&w[n * KTOT + k]);
        float w1 = __ldg(&w[n * KTOT + k + 1]);
        ((uint32_t*)g_wfrag)[((sp * 8 + nt) * 32 + lane) * 4 + ks * 2 + reg] =
            pack_f16x2(w0, w1);
    }
    if (idx < CIN * NBINS) out_hist[idx] = 0.0f;
}

// ---------------------------------------------------------------------------
// Implicit-GEMM conv via mma.sync fp16 (m16n8k16), f32 accumulate.
// CTA: 128 px x 64 couts, 256 threads, 8 warps: (w&3)->M 32, (w>>2)->N 32.
// KC=96, 6 chunks, one barrier each. A staged RAW f32 [k][m] (pitch 132):
//   producer: warp w fills k-rows w*12..w*12+11; lane = pixel (coalesced
//   LDG.32, 1 wavefront) -> STS.32 consecutive (conflict-free).
//   consumer: 8 conflict-free LDS.32 + 4 cvt packs per fragment.
// ---------------------------------------------------------------------------
__global__ __launch_bounds__(256, 2)
void conv_mma_kernel(const float* __restrict__ x,
                     const float* __restrict__ bias,
                     float* __restrict__ y) {
    extern __shared__ __align__(16) float dsm[];   // 2 x BUFW; E aliases

    const int tid  = threadIdx.x;
    const int w    = tid >> 5;
    const int lane = tid & 31;
    const int g    = lane >> 2;
    const int klo  = lane & 3;

    const int b    = blockIdx.x / NTILE;
    const int pix0 = (blockIdx.x % NTILE) * TILE_M;
    const float* xb = x + (size_t)b * CIN * NPIX;

    // ---- producer: 4 pixel segments (m = seg*32 + lane) ----
    const float* P[4];
    unsigned smask[4];
    #pragma unroll
    for (int seg = 0; seg < 4; seg++) {
        int pm = pix0 + seg * 32 + lane;
        int hm = pm / HW, wm = pm - hm * HW;
        P[seg] = xb + pm - HW - 1;
        unsigned tm = 0;
        #pragma unroll
        for (int t = 0; t < 9; t++) {
            int dh = t / 3, dw = t - dh * 3;
            if (hm + dh >= 1 && hm + dh <= HW && wm + dw >= 1 && wm + dw <= HW)
                tm |= 1u << t;
        }
        smask[seg] = tm;
    }

    // fill chunk c's buffer: warp w does k-rows w*12 .. w*12+11
    auto fill = [&](int c) {
        float* buf = dsm + (c & 1) * BUFW;
        const int klbase = w * 12;
        #pragma unroll
        for (int kr = 0; kr < 12; kr++) {
            const int kl  = klbase + kr;          // chunk-local k row
            const int k   = c * KC + kl;          // global k
            const int ci  = (k * 7282) >> 16;     // k/9 for k<576
            const int tap = k - 9 * ci;
            const int dh  = (tap * 11) >> 5;      // tap/3
            const int dw  = tap - 3 * dh;
            const int delta = ci * NPIX + dh * HW + dw;
            float* dst = buf + kl * MPITCH + lane;
            #pragma unroll
            for (int seg = 0; seg < 4; seg++) {
                float v = ((smask[seg] >> tap) & 1u) ? __ldg(P[seg] + delta)
                                                     : 0.0f;
                dst[seg * 32] = v;
            }
        }
    };

    const int wm2 = (w & 3) * 2;
    const int wn4 = (w >> 2) * 4;

    float d[2][4][4];
    #pragma unroll
    for (int mt = 0; mt < 2; mt++)
        #pragma unroll
        for (int nt = 0; nt < 4; nt++)
            #pragma unroll
            for (int k = 0; k < 4; k++) d[mt][nt][k] = 0.0f;

    fill(0);
    __syncthreads();

    for (int c = 0; c < NCHUNK; c++) {
        if (c + 1 < NCHUNK) fill(c + 1);     // other buffer; overlaps MMA below

        const float* buf = dsm + (c & 1) * BUFW;
        #pragma unroll
        for (int kp = 0; kp < 3; kp++) {
            const int sp = c * 3 + kp;
            uint4 Bq[4];
            #pragma unroll
            for (int nt = 0; nt < 4; nt++)
                Bq[nt] = __ldg(&g_wfrag[(sp * 8 + wn4 + nt) * 32 + lane]);
            #pragma unroll
            for (int ks2 = 0; ks2 < 2; ks2++) {
                const int k0 = (kp * 2 + ks2) * 16 + 2 * klo;
                #pragma unroll
                for (int mt = 0; mt < 2; mt++) {
                    const float* bp = buf + (wm2 + mt) * 16 + g;
                    float x0 = bp[k0 * MPITCH];
                    float x1 = bp[(k0 + 1) * MPITCH];
                    float y0 = bp[k0 * MPITCH + 8];
                    float y1 = bp[(k0 + 1) * MPITCH + 8];
                    float x8 = bp[(k0 + 8) * MPITCH];
                    float x9 = bp[(k0 + 9) * MPITCH];
                    float y8 = bp[(k0 + 8) * MPITCH + 8];
                    float y9 = bp[(k0 + 9) * MPITCH + 8];
                    uint4 A;
                    A.x = pack_f16x2(x0, x1);
                    A.y = pack_f16x2(y0, y1);
                    A.z = pack_f16x2(x8, x9);
                    A.w = pack_f16x2(y8, y9);
                    #pragma unroll
                    for (int nt = 0; nt < 4; nt++) {
                        uint32_t b0 = ks2 ? Bq[nt].z : Bq[nt].x;
                        uint32_t b1 = ks2 ? Bq[nt].w : Bq[nt].y;
                        MMA_F16(d[mt][nt], A, b0, b1);
                    }
                }
            }
        }
        __syncthreads();
    }

    // ---- epilogue: stage via smem for coalesced 128B stores ----
    float breg[8];
    #pragma unroll
    for (int i = 0; i < 8; i++) breg[i] = __ldg(&bias[w * 8 + i]);

    float* E = dsm;                         // aliases buffer 0 (free now)
    const int rbase = (w & 3) * 32 + g;
    const int cbase = wn4 * 8 + klo * 2;
    #pragma unroll
    for (int mt = 0; mt < 2; mt++) {
        #pragma unroll
        for (int nt = 0; nt < 4; nt++) {
            int r0 = rbase + mt * 16;
            int c0 = cbase + nt * 8;
            E[c0 * ESTRIDE + r0]           = d[mt][nt][0];
            E[(c0 + 1) * ESTRIDE + r0]     = d[mt][nt][1];
            E[c0 * ESTRIDE + r0 + 8]       = d[mt][nt][2];
            E[(c0 + 1) * ESTRIDE + r0 + 8] = d[mt][nt][3];
        }
    }
    __syncthreads();

    float* yb = y + (size_t)b * COUT * NPIX + pix0;
    const int p4 = lane * 4;
    #pragma unroll
    for (int i = 0; i < 8; i++) {
        int co = w * 8 + i;
        float4 v = *(const float4*)&E[co * ESTRIDE + p4];
        float bv = breg[i];
        v.x += bv; v.y += bv; v.z += bv; v.w += bv;
        *(float4*)&yb[(size_t)co * NPIX + p4] = v;
    }
}

// ---------------------------------------------------------------------------
// Histogram: warp-ballot byte-SIMD separable window-sum, direct float output.
// ---------------------------------------------------------------------------
__device__ __forceinline__ unsigned zprow_calc(unsigned nib, int l) {
    unsigned nl = __shfl_sync(0xFFFFFFFFu, nib, (l == 0) ? 29 : (l - 1));
    unsigned nr = __shfl_sync(0xFFFFFFFFu, nib, (l == 27) ? 28 : ((l + 1) & 31));
    unsigned ext = ((nl >> 3) & 1u) | (nib << 1) | ((nr & 1u) << 5);
    unsigned z0 = __popc(ext & 7u);
    unsigned z1 = __popc((ext >> 1) & 7u);
    unsigned z2 = __popc((ext >> 2) & 7u);
    unsigned z3 = __popc((ext >> 3) & 7u);
    return z0 | (z1 << 8) | (z2 << 16) | (z3 << 24);
}

__global__ __launch_bounds__(256)
void hist_count_kernel(const float* __restrict__ x, const float* __restrict__ w,
                       float* __restrict__ out_hist) {
    const int bid = blockIdx.x;
    const int rc = bid & 3;
    const int c  = (bid >> 2) & 63;
    const int b  = bid >> 8;

    __shared__ int sbin[NBINS];
    const int tid = threadIdx.x;
    if (tid < NBINS) sbin[tid] = 0;

    bool anywz = false;
    #pragma unroll
    for (int k = 0; k < KK; k++) anywz |= (__ldg(&w[c * KK + k]) == 0.0f);
    __syncthreads();

    const float* xp = x + (size_t)(b * CIN + c) * NPIX;

    if (!anywz) {
        const int wd = tid >> 5, l = tid & 31;
        const int half = wd & 1, sub = wd >> 1;
        const int r0 = rc * 56 + sub * 14;
        int colb; bool ldok;
        if (l < 28)      { colb = 112 * half + 4 * l;  ldok = true; }
        else if (l == 28){ colb = 112 * half + 112;    ldok = (half == 0); }
        else if (l == 29){ colb = 112 * half - 4;      ldok = (half == 1); }
        else             { colb = 0;                   ldok = false; }

        auto vget = [&](int row) -> float4 {
            if (ldok && row >= 0 && row < HW)
                return __ldg((const float4*)(xp + row * HW + colb));
            return make_float4(1.f, 1.f, 1.f, 1.f);
        };
        auto nibof = [&](int row, float4 v) -> unsigned {
            if (!ldok || row < 0 || row >= HW) return 0xFu;
            return (v.x == 0.f ? 1u : 0u) | (v.y == 0.f ? 2u : 0u) |
                   (v.z == 0.f ? 4u : 0u) | (v.w == 0.f ? 8u : 0u);
        };

        int cnt0 = 0;
        float4 va = vget(r0 - 1);
        float4 vb = vget(r0);
        float4 vnext = vget(r0 + 1);
        unsigned zpm = zprow_calc(nibof(r0 - 1, va), l);
        unsigned zpc = zprow_calc(nibof(r0, vb), l);

        for (int r = r0; r < r0 + 14; r++) {
            float4 vd = vget(r + 2);
            unsigned zpn = zprow_calc(nibof(r + 1, vnext), l);
            unsigned z4 = zpm + zpc + zpn;   // byte-SIMD (max 9/byte)
            if (l < 28) {
                if (z4 == 0) cnt0 += 4;
                else {
                    #pragma unroll
                    for (int j = 0; j < 4; j++) {
                        unsigned bz = (z4 >> (8 * j)) & 0xFFu;
                        if (bz == 0) cnt0++;
                        else atomicAdd(&sbin[bz], 1);
                    }
                }
            }
            zpm = zpc; zpc = zpn; vnext = vd;
        }
        if (l < 28 && cnt0) atomicAdd(&sbin[0], cnt0);
    } else {
        bool wz[KK];
        #pragma unroll
        for (int k = 0; k < KK; k++) wz[k] = (__ldg(&w[c * KK + k]) == 0.0f);
        const int col = tid;
        const int r0q = rc * 56;
        if (col < HW) {
            for (int row = r0q; row < r0q + 56; row++) {
                int z = 0;
                #pragma unroll
                for (int kh = 0; kh < 3; kh++)
                    #pragma unroll
                    for (int kw = 0; kw < 3; kw++) {
                        int gy = row + kh - 1, gx = col + kw - 1;
                        bool zero = (gy < 0 || gy >= HW || gx < 0 || gx >= HW)
                            ? true
                            : (wz[kh * 3 + kw] || __ldg(&xp[gy * HW + gx]) == 0.0f);
                        z += zero ? 1 : 0;
                    }
                atomicAdd(&sbin[z], 1);
            }
        }
    }

    __syncthreads();
    if (tid < NBINS && sbin[tid])
        atomicAdd(&out_hist[c * NBINS + tid], (float)sbin[tid]);
}

// no-op padding kernel: keeps ncu's capture (launch #8) on conv_mma_kernel
__global__ void nop_kernel() {}

// ---------------------------------------------------------------------------
extern "C" void kernel_launch(void* const* d_in, const int* in_sizes, int n_in,
                              void* d_out, int out_size) {
    const float* x    = (const float*)d_in[0];   // (4,64,224,224)
    const float* wgt  = (const float*)d_in[1];   // (64,64,3,3)
    const float* bias = (const float*)d_in[2];   // (64,)
    float* y    = (float*)d_out;
    float* hist = (float*)d_out + (size_t)Y_ELEMS;

    static int smem_set = 0;
    if (!smem_set) {
        cudaFuncSetAttribute(conv_mma_kernel,
                             cudaFuncAttributeMaxDynamicSharedMemorySize,
                             SMEM_SZ);
        smem_set = 1;
    }

    // order chosen so launch #8 (ncu capture point) is conv_mma_kernel
    repack_w_kernel<<<(18 * 8 * 32 * 4 + 255) / 256, 256>>>(wgt, hist);
    nop_kernel<<<1, 32>>>();
    hist_count_kernel<<<BATCH * CIN * 4, 256>>>(x, wgt, hist);
    conv_mma_kernel<<<NCONV, 256, SMEM_SZ>>>(x, bias, y);
}

// round 16
// speedup vs baseline: 1.1541x; 1.1032x over previous
#include <cuda_runtime.h>
#include <cstdint>

#define BATCH 4
#define CIN   64
#define COUT  64
#define HW    224
#define NPIX  (HW * HW)          // 50176
#define KK    9
#define NBINS 10
#define KTOT  (CIN * KK)         // 576
#define KC    96
#define NCHUNK (KTOT / KC)       // 6
#define TILE_M 128
#define NTILE (NPIX / TILE_M)    // 392
#define NCONV (BATCH * NTILE)    // 1568
#define Y_ELEMS (BATCH * COUT * NPIX)
#define ESTRIDE 132              // epilogue smem stride (conflict-free)

#define MP2   136                // packed A pitch (banks: 8*klo+g, distinct)
#define KROWS 48                 // k-pair rows per chunk (KC/2)
#define BUF2  (KROWS * MP2)      // uints per buffer (6528)
#define SMEM_SZ (2 * BUF2 * 4)   // 52224 B

// B fragments as uint4: [sp 18][nt 8][lane 32] -> (ks0.r0, ks0.r1, ks1.r0, ks1.r1)
__device__ uint4 g_wfrag[18 * 8 * 32];

__device__ __forceinline__ uint32_t pack_f16x2(float lo, float hi) {
    uint32_t d;
    asm("cvt.rn.f16x2.f32 %0, %1, %2;" : "=r"(d) : "f"(hi), "f"(lo));
    return d;
}

#define MMA_F16(d, a, b0, b1) \
    asm volatile("mma.sync.aligned.m16n8k16.row.col.f32.f16.f16.f32 " \
        "{%0,%1,%2,%3}, {%4,%5,%6,%7}, {%8,%9}, {%0,%1,%2,%3};" \
        : "+f"((d)[0]), "+f"((d)[1]), "+f"((d)[2]), "+f"((d)[3]) \
        : "r"((a).x), "r"((a).y), "r"((a).z), "r"((a).w), \
          "r"(b0), "r"(b1))

// ---------------------------------------------------------------------------
// Repack W (64,576) -> paired m16n8k16 B-fragment order fp16; zero hist out.
// ---------------------------------------------------------------------------
__global__ void repack_w_kernel(const float* __restrict__ w,
                                float* __restrict__ out_hist) {
    int idx = blockIdx.x * blockDim.x + threadIdx.x;
    if (idx < 18 * 8 * 32 * 4) {
        int reg  = idx & 1;
        int ks   = (idx >> 1) & 1;
        int lane = (idx >> 2) & 31;
        int nt   = (idx >> 7) & 7;
        int sp   = idx >> 10;
        int n = nt * 8 + (lane >> 2);
        int k = sp * 32 + ks * 16 + (lane & 3) * 2 + reg * 8;
        float w0 = __ldg(&w[n * KTOT + k]);
        float w1 = __ldg(&w[n * KTOT + k + 1]);
        ((uint32_t*)g_wfrag)[((sp * 8 + nt) * 32 + lane) * 4 + ks * 2 + reg] =
            pack_f16x2(w0, w1);
    }
    if (idx < CIN * NBINS) out_hist[idx] = 0.0f;
}

// ---------------------------------------------------------------------------
// Implicit-GEMM conv via mma.sync fp16 (m16n8k16), f32 accumulate.
// CTA: 128 px x 64 couts, 256 threads, 8 warps: (w&3)->M 32, (w>>2)->N 32.
// KC=96, 6 chunks, one barrier each. A staged as f16x2 k-PAIRS [k/2][m]:
//   producer: warp w fills pair-rows w*6..w*6+5; lane = pixel (coalesced
//   LDG.32 x2 -> pack -> 1 STS.32). consumer: 4 conflict-free LDS.32 per
//   fragment, ZERO cvt.
// ---------------------------------------------------------------------------
__global__ __launch_bounds__(256, 2)
void conv_mma_kernel(const float* __restrict__ x,
                     const float* __restrict__ bias,
                     float* __restrict__ y) {
    extern __shared__ __align__(16) float dsm[];   // 2 x BUF2 uints; E aliases
    uint32_t* sbuf = (uint32_t*)dsm;

    const int tid  = threadIdx.x;
    const int w    = tid >> 5;
    const int lane = tid & 31;
    const int g    = lane >> 2;
    const int klo  = lane & 3;

    const int b    = blockIdx.x / NTILE;
    const int pix0 = (blockIdx.x % NTILE) * TILE_M;
    const float* xb = x + (size_t)b * CIN * NPIX;

    // ---- producer: 4 pixel segments (m = seg*32 + lane) ----
    const float* P[4];
    unsigned smask[4];
    #pragma unroll
    for (int seg = 0; seg < 4; seg++) {
        int pm = pix0 + seg * 32 + lane;
        int hm = pm / HW, wm = pm - hm * HW;
        P[seg] = xb + pm - HW - 1;
        unsigned tm = 0;
        #pragma unroll
        for (int t = 0; t < 9; t++) {
            int dh = t / 3, dw = t - dh * 3;
            if (hm + dh >= 1 && hm + dh <= HW && wm + dw >= 1 && wm + dw <= HW)
                tm |= 1u << t;
        }
        smask[seg] = tm;
    }

    // fill chunk c: warp w does k-pair rows w*6 .. w*6+5
    auto fill = [&](int c) {
        uint32_t* buf = sbuf + (c & 1) * BUF2;
        const int base = w * 6;
        #pragma unroll
        for (int kr = 0; kr < 6; kr++) {
            const int kl2 = base + kr;
            const int k0  = c * KC + kl2 * 2;
            const int k1  = k0 + 1;
            const int ci0  = (k0 * 7282) >> 16;     // k/9 for k<576
            const int tap0 = k0 - 9 * ci0;
            const int ci1  = (k1 * 7282) >> 16;
            const int tap1 = k1 - 9 * ci1;
            const int dh0 = (tap0 * 11) >> 5, dw0 = tap0 - 3 * dh0;
            const int dh1 = (tap1 * 11) >> 5, dw1 = tap1 - 3 * dh1;
            const int d0 = ci0 * NPIX + dh0 * HW + dw0;
            const int d1 = ci1 * NPIX + dh1 * HW + dw1;
            uint32_t* dst = buf + kl2 * MP2 + lane;
            #pragma unroll
            for (int seg = 0; seg < 4; seg++) {
                float v0 = ((smask[seg] >> tap0) & 1u) ? __ldg(P[seg] + d0)
                                                       : 0.0f;
                float v1 = ((smask[seg] >> tap1) & 1u) ? __ldg(P[seg] + d1)
                                                       : 0.0f;
                dst[seg * 32] = pack_f16x2(v0, v1);
            }
        }
    };

    const int wm2 = (w & 3) * 2;
    const int wn4 = (w >> 2) * 4;

    float d[2][4][4];
    #pragma unroll
    for (int mt = 0; mt < 2; mt++)
        #pragma unroll
        for (int nt = 0; nt < 4; nt++)
            #pragma unroll
            for (int k = 0; k < 4; k++) d[mt][nt][k] = 0.0f;

    fill(0);
    __syncthreads();

    for (int c = 0; c < NCHUNK; c++) {
        if (c + 1 < NCHUNK) fill(c + 1);     // other buffer; overlaps MMA below

        const uint32_t* buf = sbuf + (c & 1) * BUF2;
        #pragma unroll
        for (int kp = 0; kp < 3; kp++) {
            const int sp = c * 3 + kp;
            uint4 Bq[4];
            #pragma unroll
            for (int nt = 0; nt < 4; nt++)
                Bq[nt] = __ldg(&g_wfrag[(sp * 8 + wn4 + nt) * 32 + lane]);
            #pragma unroll
            for (int ks2 = 0; ks2 < 2; ks2++) {
                const int kr = (kp * 2 + ks2) * 8 + klo;    // k-pair row
                #pragma unroll
                for (int mt = 0; mt < 2; mt++) {
                    const uint32_t* bp = buf + kr * MP2 + (wm2 + mt) * 16 + g;
                    uint4 A;
                    A.x = bp[0];            // (k0,k0+1)  row g
                    A.y = bp[8];            // (k0,k0+1)  row g+8
                    A.z = bp[4 * MP2];      // (k0+8,k0+9) row g
                    A.w = bp[4 * MP2 + 8];  // (k0+8,k0+9) row g+8
                    #pragma unroll
                    for (int nt = 0; nt < 4; nt++) {
                        uint32_t b0 = ks2 ? Bq[nt].z : Bq[nt].x;
                        uint32_t b1 = ks2 ? Bq[nt].w : Bq[nt].y;
                        MMA_F16(d[mt][nt], A, b0, b1);
                    }
                }
            }
        }
        __syncthreads();
    }

    // ---- epilogue: stage via smem for coalesced 128B stores ----
    float breg[8];
    #pragma unroll
    for (int i = 0; i < 8; i++) breg[i] = __ldg(&bias[w * 8 + i]);

    float* E = dsm;                         // aliases both buffers (free now)
    const int rbase = (w & 3) * 32 + g;
    const int cbase = wn4 * 8 + klo * 2;
    #pragma unroll
    for (int mt = 0; mt < 2; mt++) {
        #pragma unroll
        for (int nt = 0; nt < 4; nt++) {
            int r0 = rbase + mt * 16;
            int c0 = cbase + nt * 8;
            E[c0 * ESTRIDE + r0]           = d[mt][nt][0];
            E[(c0 + 1) * ESTRIDE + r0]     = d[mt][nt][1];
            E[c0 * ESTRIDE + r0 + 8]       = d[mt][nt][2];
            E[(c0 + 1) * ESTRIDE + r0 + 8] = d[mt][nt][3];
        }
    }
    __syncthreads();

    float* yb = y + (size_t)b * COUT * NPIX + pix0;
    const int p4 = lane * 4;
    #pragma unroll
    for (int i = 0; i < 8; i++) {
        int co = w * 8 + i;
        float4 v = *(const float4*)&E[co * ESTRIDE + p4];
        float bv = breg[i];
        v.x += bv; v.y += bv; v.z += bv; v.w += bv;
        *(float4*)&yb[(size_t)co * NPIX + p4] = v;
    }
}

// ---------------------------------------------------------------------------
// Histogram: warp-ballot byte-SIMD separable window-sum, direct float output.
// ---------------------------------------------------------------------------
__device__ __forceinline__ unsigned zprow_calc(unsigned nib, int l) {
    unsigned nl = __shfl_sync(0xFFFFFFFFu, nib, (l == 0) ? 29 : (l - 1));
    unsigned nr = __shfl_sync(0xFFFFFFFFu, nib, (l == 27) ? 28 : ((l + 1) & 31));
    unsigned ext = ((nl >> 3) & 1u) | (nib << 1) | ((nr & 1u) << 5);
    unsigned z0 = __popc(ext & 7u);
    unsigned z1 = __popc((ext >> 1) & 7u);
    unsigned z2 = __popc((ext >> 2) & 7u);
    unsigned z3 = __popc((ext >> 3) & 7u);
    return z0 | (z1 << 8) | (z2 << 16) | (z3 << 24);
}

__global__ __launch_bounds__(256)
void hist_count_kernel(const float* __restrict__ x, const float* __restrict__ w,
                       float* __restrict__ out_hist) {
    const int bid = blockIdx.x;
    const int rc = bid & 3;
    const int c  = (bid >> 2) & 63;
    const int b  = bid >> 8;

    __shared__ int sbin[NBINS];
    const int tid = threadIdx.x;
    if (tid < NBINS) sbin[tid] = 0;

    bool anywz = false;
    #pragma unroll
    for (int k = 0; k < KK; k++) anywz |= (__ldg(&w[c * KK + k]) == 0.0f);
    __syncthreads();

    const float* xp = x + (size_t)(b * CIN + c) * NPIX;

    if (!anywz) {
        const int wd = tid >> 5, l = tid & 31;
        const int half = wd & 1, sub = wd >> 1;
        const int r0 = rc * 56 + sub * 14;
        int colb; bool ldok;
        if (l < 28)      { colb = 112 * half + 4 * l;  ldok = true; }
        else if (l == 28){ colb = 112 * half + 112;    ldok = (half == 0); }
        else if (l == 29){ colb = 112 * half - 4;      ldok = (half == 1); }
        else             { colb = 0;                   ldok = false; }

        auto vget = [&](int row) -> float4 {
            if (ldok && row >= 0 && row < HW)
                return __ldg((const float4*)(xp + row * HW + colb));
            return make_float4(1.f, 1.f, 1.f, 1.f);
        };
        auto nibof = [&](int row, float4 v) -> unsigned {
            if (!ldok || row < 0 || row >= HW) return 0xFu;
            return (v.x == 0.f ? 1u : 0u) | (v.y == 0.f ? 2u : 0u) |
                   (v.z == 0.f ? 4u : 0u) | (v.w == 0.f ? 8u : 0u);
        };

        int cnt0 = 0;
        float4 va = vget(r0 - 1);
        float4 vb = vget(r0);
        float4 vnext = vget(r0 + 1);
        unsigned zpm = zprow_calc(nibof(r0 - 1, va), l);
        unsigned zpc = zprow_calc(nibof(r0, vb), l);

        for (int r = r0; r < r0 + 14; r++) {
            float4 vd = vget(r + 2);
            unsigned zpn = zprow_calc(nibof(r + 1, vnext), l);
            unsigned z4 = zpm + zpc + zpn;   // byte-SIMD (max 9/byte)
            if (l < 28) {
                if (z4 == 0) cnt0 += 4;
                else {
                    #pragma unroll
                    for (int j = 0; j < 4; j++) {
                        unsigned bz = (z4 >> (8 * j)) & 0xFFu;
                        if (bz == 0) cnt0++;
                        else atomicAdd(&sbin[bz], 1);
                    }
                }
            }
            zpm = zpc; zpc = zpn; vnext = vd;
        }
        if (l < 28 && cnt0) atomicAdd(&sbin[0], cnt0);
    } else {
        bool wz[KK];
        #pragma unroll
        for (int k = 0; k < KK; k++) wz[k] = (__ldg(&w[c * KK + k]) == 0.0f);
        const int col = tid;
        const int r0q = rc * 56;
        if (col < HW) {
            for (int row = r0q; row < r0q + 56; row++) {
                int z = 0;
                #pragma unroll
                for (int kh = 0; kh < 3; kh++)
                    #pragma unroll
                    for (int kw = 0; kw < 3; kw++) {
                        int gy = row + kh - 1, gx = col + kw - 1;
                        bool zero = (gy < 0 || gy >= HW || gx < 0 || gx >= HW)
                            ? true
                            : (wz[kh * 3 + kw] || __ldg(&xp[gy * HW + gx]) == 0.0f);
                        z += zero ? 1 : 0;
                    }
                atomicAdd(&sbin[z], 1);
            }
        }
    }

    __syncthreads();
    if (tid < NBINS && sbin[tid])
        atomicAdd(&out_hist[c * NBINS + tid], (float)sbin[tid]);
}

// no-op padding kernel: keeps ncu's capture (launch #8) on conv_mma_kernel
__global__ void nop_kernel() {}

// ---------------------------------------------------------------------------
extern "C" void kernel_launch(void* const* d_in, const int* in_sizes, int n_in,
                              void* d_out, int out_size) {
    const float* x    = (const float*)d_in[0];   // (4,64,224,224)
    const float* wgt  = (const float*)d_in[1];   // (64,64,3,3)
    const float* bias = (const float*)d_in[2];   // (64,)
    float* y    = (float*)d_out;
    float* hist = (float*)d_out + (size_t)Y_ELEMS;

    static int smem_set = 0;
    if (!smem_set) {
        cudaFuncSetAttribute(conv_mma_kernel,
                             cudaFuncAttributeMaxDynamicSharedMemorySize,
                             SMEM_SZ);
        smem_set = 1;
    }

    // order chosen so launch #8 (ncu capture point) is conv_mma_kernel
    repack_w_kernel<<<(18 * 8 * 32 * 4 + 255) / 256, 256>>>(wgt, hist);
    nop_kernel<<<1, 32>>>();
    hist_count_kernel<<<BATCH * CIN * 4, 256>>>(x, wgt, hist);
    conv_mma_kernel<<<NCONV, 256, SMEM_SZ>>>(x, bias, y);
}

// round 17
// speedup vs baseline: 1.1711x; 1.0147x over previous
#include <cuda_runtime.h>
#include <cstdint>

#define BATCH 4
#define CIN   64
#define COUT  64
#define HW    224
#define NPIX  (HW * HW)          // 50176
#define KK    9
#define NBINS 10
#define KTOT  (CIN * KK)         // 576
#define KC    96
#define NCHUNK (KTOT / KC)       // 6
#define TILE_M 128
#define NTILE (NPIX / TILE_M)    // 392
#define NCONV (BATCH * NTILE)    // 1568
#define PGRID 296                // persistent grid: 2 CTAs x 148 SMs
#define Y_ELEMS (BATCH * COUT * NPIX)
#define ESTRIDE 132              // epilogue smem stride (conflict-free)

#define MP2   136                // packed A pitch (banks: 8*klo+g, distinct)
#define KROWS 48                 // k-pair rows per chunk (KC/2)
#define BUF2  (KROWS * MP2)      // uints per buffer (6528)
#define SMEM_SZ (2 * BUF2 * 4)   // 52224 B

// B fragments as uint4: [sp 18][nt 8][lane 32] -> (ks0.r0, ks0.r1, ks1.r0, ks1.r1)
__device__ uint4 g_wfrag[18 * 8 * 32];

__device__ __forceinline__ uint32_t pack_f16x2(float lo, float hi) {
    uint32_t d;
    asm("cvt.rn.f16x2.f32 %0, %1, %2;" : "=r"(d) : "f"(hi), "f"(lo));
    return d;
}

#define MMA_F16(d, a, b0, b1) \
    asm volatile("mma.sync.aligned.m16n8k16.row.col.f32.f16.f16.f32 " \
        "{%0,%1,%2,%3}, {%4,%5,%6,%7}, {%8,%9}, {%0,%1,%2,%3};" \
        : "+f"((d)[0]), "+f"((d)[1]), "+f"((d)[2]), "+f"((d)[3]) \
        : "r"((a).x), "r"((a).y), "r"((a).z), "r"((a).w), \
          "r"(b0), "r"(b1))

// ---------------------------------------------------------------------------
// Repack W (64,576) -> paired m16n8k16 B-fragment order fp16; zero hist out.
// ---------------------------------------------------------------------------
__global__ void repack_w_kernel(const float* __restrict__ w,
                                float* __restrict__ out_hist) {
    int idx = blockIdx.x * blockDim.x + threadIdx.x;
    if (idx < 18 * 8 * 32 * 4) {
        int reg  = idx & 1;
        int ks   = (idx >> 1) & 1;
        int lane = (idx >> 2) & 31;
        int nt   = (idx >> 7) & 7;
        int sp   = idx >> 10;
        int n = nt * 8 + (lane >> 2);
        int k = sp * 32 + ks * 16 + (lane & 3) * 2 + reg * 8;
        float w0 = __ldg(&w[n * KTOT + k]);
        float w1 = __ldg(&w[n * KTOT + k + 1]);
        ((uint32_t*)g_wfrag)[((sp * 8 + nt) * 32 + lane) * 4 + ks * 2 + reg] =
            pack_f16x2(w0, w1);
    }
    if (idx < CIN * NBINS) out_hist[idx] = 0.0f;
}

// ---------------------------------------------------------------------------
// Implicit-GEMM conv via mma.sync fp16 (m16n8k16), f32 accumulate.
// PERSISTENT: 296 CTAs (2/SM, one wave), each loops over ~5.3 tiles.
// Per tile: 128 px x 64 couts, 8 warps: (w&3)->M 32, (w>>2)->N 32.
// KC=96, 6 chunks, one barrier each. A staged as f16x2 k-pairs [k/2][m].
// ---------------------------------------------------------------------------
__global__ __launch_bounds__(256, 2)
void conv_mma_kernel(const float* __restrict__ x,
                     const float* __restrict__ bias,
                     float* __restrict__ y) {
    extern __shared__ __align__(16) float dsm[];   // 2 x BUF2 uints; E aliases
    uint32_t* sbuf = (uint32_t*)dsm;

    const int tid  = threadIdx.x;
    const int w    = tid >> 5;
    const int lane = tid & 31;
    const int g    = lane >> 2;
    const int klo  = lane & 3;

    const int wm2 = (w & 3) * 2;
    const int wn4 = (w >> 2) * 4;

    // bias registers: constant across tiles
    float breg[8];
    #pragma unroll
    for (int i = 0; i < 8; i++) breg[i] = __ldg(&bias[w * 8 + i]);

    for (int t = blockIdx.x; t < NCONV; t += PGRID) {
        const int b    = t / NTILE;
        const int pix0 = (t % NTILE) * TILE_M;
        const float* xb = x + (size_t)b * CIN * NPIX;

        // ---- producer: 4 pixel segments (m = seg*32 + lane) ----
        const float* P[4];
        unsigned smask[4];
        #pragma unroll
        for (int seg = 0; seg < 4; seg++) {
            int pm = pix0 + seg * 32 + lane;
            int hm = pm / HW, wm = pm - hm * HW;
            P[seg] = xb + pm - HW - 1;
            unsigned tm = 0;
            #pragma unroll
            for (int tt = 0; tt < 9; tt++) {
                int dh = tt / 3, dw = tt - dh * 3;
                if (hm + dh >= 1 && hm + dh <= HW &&
                    wm + dw >= 1 && wm + dw <= HW)
                    tm |= 1u << tt;
            }
            smask[seg] = tm;
        }

        // fill chunk c: warp w does k-pair rows w*6 .. w*6+5
        auto fill = [&](int c) {
            uint32_t* buf = sbuf + (c & 1) * BUF2;
            const int base = w * 6;
            #pragma unroll
            for (int kr = 0; kr < 6; kr++) {
                const int kl2 = base + kr;
                const int k0  = c * KC + kl2 * 2;
                const int k1  = k0 + 1;
                const int ci0  = (k0 * 7282) >> 16;   // k/9 for k<576
                const int tap0 = k0 - 9 * ci0;
                const int ci1  = (k1 * 7282) >> 16;
                const int tap1 = k1 - 9 * ci1;
                const int dh0 = (tap0 * 11) >> 5, dw0 = tap0 - 3 * dh0;
                const int dh1 = (tap1 * 11) >> 5, dw1 = tap1 - 3 * dh1;
                const int d0 = ci0 * NPIX + dh0 * HW + dw0;
                const int d1 = ci1 * NPIX + dh1 * HW + dw1;
                uint32_t* dst = buf + kl2 * MP2 + lane;
                #pragma unroll
                for (int seg = 0; seg < 4; seg++) {
                    float v0 = ((smask[seg] >> tap0) & 1u) ? __ldg(P[seg] + d0)
                                                           : 0.0f;
                    float v1 = ((smask[seg] >> tap1) & 1u) ? __ldg(P[seg] + d1)
                                                           : 0.0f;
                    dst[seg * 32] = pack_f16x2(v0, v1);
                }
            }
        };

        float d[2][4][4];
        #pragma unroll
        for (int mt = 0; mt < 2; mt++)
            #pragma unroll
            for (int nt = 0; nt < 4; nt++)
                #pragma unroll
                for (int k = 0; k < 4; k++) d[mt][nt][k] = 0.0f;

        fill(0);
        __syncthreads();

        for (int c = 0; c < NCHUNK; c++) {
            if (c + 1 < NCHUNK) fill(c + 1);   // other buffer; overlaps MMA

            const uint32_t* buf = sbuf + (c & 1) * BUF2;
            #pragma unroll
            for (int kp = 0; kp < 3; kp++) {
                const int sp = c * 3 + kp;
                uint4 Bq[4];
                #pragma unroll
                for (int nt = 0; nt < 4; nt++)
                    Bq[nt] = __ldg(&g_wfrag[(sp * 8 + wn4 + nt) * 32 + lane]);
                #pragma unroll
                for (int ks2 = 0; ks2 < 2; ks2++) {
                    const int kr = (kp * 2 + ks2) * 8 + klo;   // k-pair row
                    #pragma unroll
                    for (int mt = 0; mt < 2; mt++) {
                        const uint32_t* bp =
                            buf + kr * MP2 + (wm2 + mt) * 16 + g;
                        uint4 A;
                        A.x = bp[0];            // (k0,k0+1)  row g
                        A.y = bp[8];            // (k0,k0+1)  row g+8
                        A.z = bp[4 * MP2];      // (k0+8,k0+9) row g
                        A.w = bp[4 * MP2 + 8];  // (k0+8,k0+9) row g+8
                        #pragma unroll
                        for (int nt = 0; nt < 4; nt++) {
                            uint32_t b0 = ks2 ? Bq[nt].z : Bq[nt].x;
                            uint32_t b1 = ks2 ? Bq[nt].w : Bq[nt].y;
                            MMA_F16(d[mt][nt], A, b0, b1);
                        }
                    }
                }
            }
            __syncthreads();
        }

        // ---- epilogue: stage via smem for coalesced 128B stores ----
        float* E = dsm;                       // aliases buffers (free now)
        const int rbase = (w & 3) * 32 + g;
        const int cbase = wn4 * 8 + klo * 2;
        #pragma unroll
        for (int mt = 0; mt < 2; mt++) {
            #pragma unroll
            for (int nt = 0; nt < 4; nt++) {
                int r0 = rbase + mt * 16;
                int c0 = cbase + nt * 8;
                E[c0 * ESTRIDE + r0]           = d[mt][nt][0];
                E[(c0 + 1) * ESTRIDE + r0]     = d[mt][nt][1];
                E[c0 * ESTRIDE + r0 + 8]       = d[mt][nt][2];
                E[(c0 + 1) * ESTRIDE + r0 + 8] = d[mt][nt][3];
            }
        }
        __syncthreads();

        float* yb = y + (size_t)b * COUT * NPIX + pix0;
        const int p4 = lane * 4;
        #pragma unroll
        for (int i = 0; i < 8; i++) {
            int co = w * 8 + i;
            float4 v = *(const float4*)&E[co * ESTRIDE + p4];
            float bv = breg[i];
            v.x += bv; v.y += bv; v.z += bv; v.w += bv;
            *(float4*)&yb[(size_t)co * NPIX + p4] = v;
        }
        __syncthreads();   // protect E reads before next tile's fill overwrites
    }
}

// ---------------------------------------------------------------------------
// Histogram: warp-ballot byte-SIMD separable window-sum, direct float output.
// ---------------------------------------------------------------------------
__device__ __forceinline__ unsigned zprow_calc(unsigned nib, int l) {
    unsigned nl = __shfl_sync(0xFFFFFFFFu, nib, (l == 0) ? 29 : (l - 1));
    unsigned nr = __shfl_sync(0xFFFFFFFFu, nib, (l == 27) ? 28 : ((l + 1) & 31));
    unsigned ext = ((nl >> 3) & 1u) | (nib << 1) | ((nr & 1u) << 5);
    unsigned z0 = __popc(ext & 7u);
    unsigned z1 = __popc((ext >> 1) & 7u);
    unsigned z2 = __popc((ext >> 2) & 7u);
    unsigned z3 = __popc((ext >> 3) & 7u);
    return z0 | (z1 << 8) | (z2 << 16) | (z3 << 24);
}

__global__ __launch_bounds__(256)
void hist_count_kernel(const float* __restrict__ x, const float* __restrict__ w,
                       float* __restrict__ out_hist) {
    const int bid = blockIdx.x;
    const int rc = bid & 3;
    const int c  = (bid >> 2) & 63;
    const int b  = bid >> 8;

    __shared__ int sbin[NBINS];
    const int tid = threadIdx.x;
    if (tid < NBINS) sbin[tid] = 0;

    bool anywz = false;
    #pragma unroll
    for (int k = 0; k < KK; k++) anywz |= (__ldg(&w[c * KK + k]) == 0.0f);
    __syncthreads();

    const float* xp = x + (size_t)(b * CIN + c) * NPIX;

    if (!anywz) {
        const int wd = tid >> 5, l = tid & 31;
        const int half = wd & 1, sub = wd >> 1;
        const int r0 = rc * 56 + sub * 14;
        int colb; bool ldok;
        if (l < 28)      { colb = 112 * half + 4 * l;  ldok = true; }
        else if (l == 28){ colb = 112 * half + 112;    ldok = (half == 0); }
        else if (l == 29){ colb = 112 * half - 4;      ldok = (half == 1); }
        else             { colb = 0;                   ldok = false; }

        auto vget = [&](int row) -> float4 {
            if (ldok && row >= 0 && row < HW)
                return __ldg((const float4*)(xp + row * HW + colb));
            return make_float4(1.f, 1.f, 1.f, 1.f);
        };
        auto nibof = [&](int row, float4 v) -> unsigned {
            if (!ldok || row < 0 || row >= HW) return 0xFu;
            return (v.x == 0.f ? 1u : 0u) | (v.y == 0.f ? 2u : 0u) |
                   (v.z == 0.f ? 4u : 0u) | (v.w == 0.f ? 8u : 0u);
        };

        int cnt0 = 0;
        float4 va = vget(r0 - 1);
        float4 vb = vget(r0);
        float4 vnext = vget(r0 + 1);
        unsigned zpm = zprow_calc(nibof(r0 - 1, va), l);
        unsigned zpc = zprow_calc(nibof(r0, vb), l);

        for (int r = r0; r < r0 + 14; r++) {
            float4 vd = vget(r + 2);
            unsigned zpn = zprow_calc(nibof(r + 1, vnext), l);
            unsigned z4 = zpm + zpc + zpn;   // byte-SIMD (max 9/byte)
            if (l < 28) {
                if (z4 == 0) cnt0 += 4;
                else {
                    #pragma unroll
                    for (int j = 0; j < 4; j++) {
                        unsigned bz = (z4 >> (8 * j)) & 0xFFu;
                        if (bz == 0) cnt0++;
                        else atomicAdd(&sbin[bz], 1);
                    }
                }
            }
            zpm = zpc; zpc = zpn; vnext = vd;
        }
        if (l < 28 && cnt0) atomicAdd(&sbin[0], cnt0);
    } else {
        bool wz[KK];
        #pragma unroll
        for (int k = 0; k < KK; k++) wz[k] = (__ldg(&w[c * KK + k]) == 0.0f);
        const int col = tid;
        const int r0q = rc * 56;
        if (col < HW) {
            for (int row = r0q; row < r0q + 56; row++) {
                int z = 0;
                #pragma unroll
                for (int kh = 0; kh < 3; kh++)
                    #pragma unroll
                    for (int kw = 0; kw < 3; kw++) {
                        int gy = row + kh - 1, gx = col + kw - 1;
                        bool zero = (gy < 0 || gy >= HW || gx < 0 || gx >= HW)
                            ? true
                            : (wz[kh * 3 + kw] || __ldg(&xp[gy * HW + gx]) == 0.0f);
                        z += zero ? 1 : 0;
                    }
                atomicAdd(&sbin[z], 1);
            }
        }
    }

    __syncthreads();
    if (tid < NBINS && sbin[tid])
        atomicAdd(&out_hist[c * NBINS + tid], (float)sbin[tid]);
}

// no-op padding kernel: keeps ncu's capture (launch #8) on conv_mma_kernel
__global__ void nop_kernel() {}

// ---------------------------------------------------------------------------
extern "C" void kernel_launch(void* const* d_in, const int* in_sizes, int n_in,
                              void* d_out, int out_size) {
    const float* x    = (const float*)d_in[0];   // (4,64,224,224)
    const float* wgt  = (const float*)d_in[1];   // (64,64,3,3)
    const float* bias = (const float*)d_in[2];   // (64,)
    float* y    = (float*)d_out;
    float* hist = (float*)d_out + (size_t)Y_ELEMS;

    static int smem_set = 0;
    if (!smem_set) {
        cudaFuncSetAttribute(conv_mma_kernel,
                             cudaFuncAttributeMaxDynamicSharedMemorySize,
                             SMEM_SZ);
        smem_set = 1;
    }

    // order chosen so launch #8 (ncu capture point) is conv_mma_kernel
    repack_w_kernel<<<(18 * 8 * 32 * 4 + 255) / 256, 256>>>(wgt, hist);
    nop_kernel<<<1, 32>>>();
    hist_count_kernel<<<BATCH * CIN * 4, 256>>>(x, wgt, hist);
    conv_mma_kernel<<<PGRID, 256, SMEM_SZ>>>(x, bias, y);
}